// round 2
// baseline (speedup 1.0000x reference)
#include <cuda_runtime.h>
#include <math.h>

// ---------------------------------------------------------------------------
// UNetMidBlockCausal3D: resnet -> causal frame attention -> resnet
// B=1, C=512, T=8, H=32, W=32  => S = 8192 positions, 32 groups of 16 chans.
// Internally channels-last: A[s, c], s = t*1024 + h*32 + w.
// No host-side device-pointer queries: kernels resolve scratch via BUF(id).
// ---------------------------------------------------------------------------

#define S_TOT 8192
#define C_DIM 512
#define NG    32
#define GSZ   16

#define BM 128
#define BN 128
#define BK 16

// Scratch (device globals; runtime allocation is forbidden)
__device__ float g_X[S_TOT * C_DIM];          // 0: residual stream
__device__ float g_N[S_TOT * C_DIM];          // 1: normalized buffer
__device__ float g_H[S_TOT * C_DIM];          // 2: conv intermediate
__device__ float g_Q[S_TOT * C_DIM];          // 3
__device__ float g_K[S_TOT * C_DIM];          // 4
__device__ float g_V[S_TOT * C_DIM];          // 5
__device__ float g_O[S_TOT * C_DIM];          // 6
__device__ float g_S[(size_t)S_TOT * S_TOT];  // 7: scores/attn (256 MB)
__device__ float g_Wc[27 * C_DIM * C_DIM];    // 8: conv weights [tap][ci][co]
__device__ float g_Wl[C_DIM * C_DIM];         // 9: linear weight [c][o]
__device__ float g_mu[NG];
__device__ float g_rs[NG];
__device__ float g_inv[S_TOT];                // per-row 1/sum(exp)

__device__ __forceinline__ float* BUF(int id) {
    switch (id) {
        case 0: return g_X;  case 1: return g_N;  case 2: return g_H;
        case 3: return g_Q;  case 4: return g_K;  case 5: return g_V;
        case 6: return g_O;  case 7: return g_S;  case 8: return g_Wc;
        default: return g_Wl;
    }
}

// ---------------------------------------------------------------------------
// 32x32-tiled transpose: dst[c][r] = src[r][c].  src is rows x cols.
// Either side may be an external pointer (non-null) or a scratch id.
// grid = (cols/32, rows/32), block = (32, 8)
// ---------------------------------------------------------------------------
__global__ void transpose_k(const float* src_ext, int src_id,
                            float* dst_ext, int dst_id,
                            int rows, int cols) {
    const float* src = src_ext ? src_ext : BUF(src_id);
    float* dst = dst_ext ? dst_ext : BUF(dst_id);
    __shared__ float tile[32][33];
    int c0 = blockIdx.x * 32, r0 = blockIdx.y * 32;
    int c = c0 + threadIdx.x;
    #pragma unroll
    for (int j = threadIdx.y; j < 32; j += 8) {
        int r = r0 + j;
        tile[j][threadIdx.x] = src[(size_t)r * cols + c];
    }
    __syncthreads();
    int r2 = r0 + threadIdx.x;
    #pragma unroll
    for (int j = threadIdx.y; j < 32; j += 8) {
        int c2 = c0 + j;
        dst[(size_t)c2 * rows + r2] = tile[threadIdx.x][j];
    }
}

// Conv weight transpose: g_Wc[tap][ci][co] = w[co][ci][tap]
__global__ void wconv_tr(const float* __restrict__ w) {
    int idx = blockIdx.x * 256 + threadIdx.x;
    int tap = idx / (C_DIM * C_DIM);
    int rem = idx - tap * (C_DIM * C_DIM);
    int ci  = rem >> 9;
    int co  = rem & 511;
    g_Wc[idx] = w[(size_t)co * (C_DIM * 27) + ci * 27 + tap];
}

// ---------------------------------------------------------------------------
// GroupNorm stats: one block per group; channels-last A[s, c].
// ---------------------------------------------------------------------------
__global__ void gn_stats(int aid) {
    const float* A = BUF(aid);
    __shared__ float sh[256], sh2[256];
    int g = blockIdx.x, tid = threadIdx.x;
    const float* base = A + g * GSZ;
    float s = 0.f, ss = 0.f;
    for (int idx = tid; idx < S_TOT * GSZ; idx += 256) {
        int r = idx >> 4, c = idx & 15;
        float v = base[(size_t)r * C_DIM + c];
        s += v; ss += v * v;
    }
    sh[tid] = s; sh2[tid] = ss;
    __syncthreads();
    for (int o = 128; o > 0; o >>= 1) {
        if (tid < o) { sh[tid] += sh[tid + o]; sh2[tid] += sh2[tid + o]; }
        __syncthreads();
    }
    if (tid == 0) {
        const float invn = 1.f / (float)(S_TOT * GSZ);
        float m   = sh[0] * invn;
        float var = sh2[0] * invn - m * m;
        g_mu[g] = m;
        g_rs[g] = rsqrtf(var + 1e-6f);
    }
}

// GroupNorm apply (+ optional SiLU); always writes g_N.
__global__ void gn_apply(int aid, const float* __restrict__ sc,
                         const float* __restrict__ bi, int do_silu) {
    const float* A = BUF(aid);
    int idx = blockIdx.x * 256 + threadIdx.x;
    float v = A[idx];
    int c = idx & 511;
    int g = c >> 4;
    float y = (v - g_mu[g]) * g_rs[g] * sc[c] + bi[c];
    if (do_silu) y = y * (1.f / (1.f + __expf(-y)));
    g_N[idx] = y;
}

// ---------------------------------------------------------------------------
// Double-buffered SGEMM (NN): C[m,n] = sum_k A[m,k]*B[k,n] (+bias) (+resid)
//   MODE 0: plain NN, A row stride lda.
//   MODE 1: conv. K = 27*512; A row gathered per tap via srow[27][BM];
//           B = g_Wc contiguous [27*512][512].
//   MODE 2: PV. A = g_S (lda = 8192), K limited to causal prefix of q-block;
//           epilogue scales row by g_inv[row].
// 128x128 tile, BK=16, 256 threads, 8x8 per thread.
// ---------------------------------------------------------------------------
template <int MODE>
__global__ __launch_bounds__(256)
void gemm_nn(int aid, int bid, const float* __restrict__ bias, int rid, int cid,
             int N, int Ktot, int lda, int ldc) {
    const float* A  = BUF(aid);
    const float* Bm = BUF(bid);
    const float* resid = (rid >= 0) ? BUF(rid) : nullptr;
    float* C = BUF(cid);

    __shared__ float As[2][BK][BM];
    __shared__ float Bs[2][BK][BN];
    __shared__ int   srow[27][BM];

    const int tid = threadIdx.x;
    const int m0 = blockIdx.y * BM;
    const int n0 = blockIdx.x * BN;
    const int tx = tid & 15, ty = tid >> 4;

    if (MODE == 1) {
        for (int i = tid; i < 27 * BM; i += 256) {
            int tap = i >> 7, r = i & 127;
            int s = m0 + r;
            int t = s >> 10, h = (s >> 5) & 31, w = s & 31;
            int kd = tap / 9, kh = (tap / 3) % 3, kw = tap % 3;
            int tt = t + kd - 2; if (tt < 0) tt = 0;
            int hh = h + kh - 1; hh = hh < 0 ? 0 : (hh > 31 ? 31 : hh);
            int ww = w + kw - 1; ww = ww < 0 ? 0 : (ww > 31 ? 31 : ww);
            srow[tap][r] = (tt << 10) | (hh << 5) | ww;
        }
        __syncthreads();
    }

    int Keff = Ktot;
    if (MODE == 2) Keff = ((m0 >> 10) + 1) << 10;  // frame-causal prefix
    const int nkt = Keff / BK;

    float acc[8][8];
    #pragma unroll
    for (int i = 0; i < 8; i++)
        #pragma unroll
        for (int j = 0; j < 8; j++) acc[i][j] = 0.f;

    float4 pa[2], pb[2];

    auto fetch = [&](int kt) {
        const int kk = kt * BK;
        #pragma unroll
        for (int it = 0; it < 2; it++) {
            int f4 = tid + it * 256;
            int row = f4 >> 2, c4 = f4 & 3;
            int arow, kloc;
            if (MODE == 1) { arow = srow[kk >> 9][row]; kloc = kk & 511; }
            else           { arow = m0 + row;           kloc = kk; }
            pa[it] = *(const float4*)(A + (size_t)arow * lda + kloc + c4 * 4);
        }
        #pragma unroll
        for (int it = 0; it < 2; it++) {
            int f4 = tid + it * 256;
            int kr = f4 >> 5, c4 = f4 & 31;
            pb[it] = *(const float4*)(Bm + (size_t)(kk + kr) * N + n0 + c4 * 4);
        }
    };
    auto stage = [&](int b) {
        #pragma unroll
        for (int it = 0; it < 2; it++) {
            int f4 = tid + it * 256;
            int row = f4 >> 2, c4 = f4 & 3;
            As[b][c4 * 4 + 0][row] = pa[it].x;
            As[b][c4 * 4 + 1][row] = pa[it].y;
            As[b][c4 * 4 + 2][row] = pa[it].z;
            As[b][c4 * 4 + 3][row] = pa[it].w;
        }
        #pragma unroll
        for (int it = 0; it < 2; it++) {
            int f4 = tid + it * 256;
            int kr = f4 >> 5, c4 = f4 & 31;
            *(float4*)&Bs[b][kr][c4 * 4] = pb[it];
        }
    };

    fetch(0);
    stage(0);
    __syncthreads();
    int cur = 0;

    for (int kt = 0; kt < nkt; kt++) {
        if (kt + 1 < nkt) fetch(kt + 1);
        #pragma unroll
        for (int k = 0; k < BK; k++) {
            float a[8], b[8];
            *(float4*)(a)     = *(const float4*)&As[cur][k][ty * 8];
            *(float4*)(a + 4) = *(const float4*)&As[cur][k][ty * 8 + 4];
            *(float4*)(b)     = *(const float4*)&Bs[cur][k][tx * 8];
            *(float4*)(b + 4) = *(const float4*)&Bs[cur][k][tx * 8 + 4];
            #pragma unroll
            for (int i = 0; i < 8; i++)
                #pragma unroll
                for (int j = 0; j < 8; j++)
                    acc[i][j] += a[i] * b[j];
        }
        if (kt + 1 < nkt) {
            stage(cur ^ 1);
            __syncthreads();
            cur ^= 1;
        }
    }

    #pragma unroll
    for (int i = 0; i < 8; i++) {
        int row = m0 + ty * 8 + i;
        float rowscale = (MODE == 2) ? g_inv[row] : 1.f;
        #pragma unroll
        for (int j = 0; j < 8; j += 4) {
            int col = n0 + tx * 8 + j;
            float4 v;
            v.x = acc[i][j];     v.y = acc[i][j + 1];
            v.z = acc[i][j + 2]; v.w = acc[i][j + 3];
            if (MODE == 2) { v.x *= rowscale; v.y *= rowscale; v.z *= rowscale; v.w *= rowscale; }
            if (bias) {
                v.x += bias[col];     v.y += bias[col + 1];
                v.z += bias[col + 2]; v.w += bias[col + 3];
            }
            if (resid) {
                float4 r = *(const float4*)(resid + (size_t)row * ldc + col);
                v.x += r.x; v.y += r.y; v.z += r.z; v.w += r.w;
            }
            *(float4*)(C + (size_t)row * ldc + col) = v;
        }
    }
}

// ---------------------------------------------------------------------------
// Scores (NT, double-buffered): g_S[q,k] = scale * sum_d Q[q,d]*K[k,d],
// only block-causal tiles (frame=1024 is a multiple of 128 => all-or-none).
// ---------------------------------------------------------------------------
__global__ __launch_bounds__(256)
void gemm_nt_scores(float scale) {
    const int m0 = blockIdx.y * BM;   // q
    const int n0 = blockIdx.x * BN;   // k
    if (n0 >= (((m0 >> 10) + 1) << 10)) return;

    __shared__ float As[2][BK][BM];
    __shared__ float Bs[2][BK][BN];
    const int tid = threadIdx.x;
    const int tx = tid & 15, ty = tid >> 4;

    float acc[8][8];
    #pragma unroll
    for (int i = 0; i < 8; i++)
        #pragma unroll
        for (int j = 0; j < 8; j++) acc[i][j] = 0.f;

    float4 pa[2], pb[2];
    auto fetch = [&](int kt) {
        const int kk = kt * BK;
        #pragma unroll
        for (int it = 0; it < 2; it++) {
            int f4 = tid + it * 256;
            int row = f4 >> 2, c4 = f4 & 3;
            pa[it] = *(const float4*)(g_Q + (size_t)(m0 + row) * C_DIM + kk + c4 * 4);
            pb[it] = *(const float4*)(g_K + (size_t)(n0 + row) * C_DIM + kk + c4 * 4);
        }
    };
    auto stage = [&](int b) {
        #pragma unroll
        for (int it = 0; it < 2; it++) {
            int f4 = tid + it * 256;
            int row = f4 >> 2, c4 = f4 & 3;
            As[b][c4 * 4 + 0][row] = pa[it].x; As[b][c4 * 4 + 1][row] = pa[it].y;
            As[b][c4 * 4 + 2][row] = pa[it].z; As[b][c4 * 4 + 3][row] = pa[it].w;
            Bs[b][c4 * 4 + 0][row] = pb[it].x; Bs[b][c4 * 4 + 1][row] = pb[it].y;
            Bs[b][c4 * 4 + 2][row] = pb[it].z; Bs[b][c4 * 4 + 3][row] = pb[it].w;
        }
    };

    fetch(0); stage(0); __syncthreads();
    int cur = 0;
    const int nkt = C_DIM / BK;
    for (int kt = 0; kt < nkt; kt++) {
        if (kt + 1 < nkt) fetch(kt + 1);
        #pragma unroll
        for (int k = 0; k < BK; k++) {
            float a[8], b[8];
            *(float4*)(a)     = *(const float4*)&As[cur][k][ty * 8];
            *(float4*)(a + 4) = *(const float4*)&As[cur][k][ty * 8 + 4];
            *(float4*)(b)     = *(const float4*)&Bs[cur][k][tx * 8];
            *(float4*)(b + 4) = *(const float4*)&Bs[cur][k][tx * 8 + 4];
            #pragma unroll
            for (int i = 0; i < 8; i++)
                #pragma unroll
                for (int j = 0; j < 8; j++)
                    acc[i][j] += a[i] * b[j];
        }
        if (kt + 1 < nkt) { stage(cur ^ 1); __syncthreads(); cur ^= 1; }
    }

    #pragma unroll
    for (int i = 0; i < 8; i++) {
        int row = m0 + ty * 8 + i;
        #pragma unroll
        for (int j = 0; j < 8; j += 4) {
            int col = n0 + tx * 8 + j;
            float4 v;
            v.x = acc[i][j] * scale;     v.y = acc[i][j + 1] * scale;
            v.z = acc[i][j + 2] * scale; v.w = acc[i][j + 3] * scale;
            *(float4*)(g_S + (size_t)row * S_TOT + col) = v;
        }
    }
}

// ---------------------------------------------------------------------------
// Softmax over causal prefix L = (frame+1)*1024.
// Leaves UNNORMALIZED exp in g_S; stores 1/sum in g_inv (PV epilogue scales).
// ---------------------------------------------------------------------------
__global__ void softmax_rows() {
    const int q = blockIdx.x;
    const int L = ((q >> 10) + 1) << 10;
    float* row = g_S + (size_t)q * S_TOT;
    __shared__ float red[256];
    const int tid = threadIdx.x;

    float m = -1e30f;
    for (int i = tid; i < L; i += 256) m = fmaxf(m, row[i]);
    red[tid] = m; __syncthreads();
    for (int o = 128; o > 0; o >>= 1) {
        if (tid < o) red[tid] = fmaxf(red[tid], red[tid + o]);
        __syncthreads();
    }
    m = red[0];
    __syncthreads();

    float s = 0.f;
    for (int i = tid; i < L; i += 256) {
        float e = __expf(row[i] - m);
        row[i] = e;
        s += e;
    }
    red[tid] = s; __syncthreads();
    for (int o = 128; o > 0; o >>= 1) {
        if (tid < o) red[tid] += red[tid + o];
        __syncthreads();
    }
    if (tid == 0) g_inv[q] = 1.f / red[0];
}

// ---------------------------------------------------------------------------
// Host orchestration — kernel launches only (graph-capture safe).
// ---------------------------------------------------------------------------
extern "C" void kernel_launch(void* const* d_in, const int* in_sizes, int n_in,
                              void* d_out, int out_size) {
    (void)in_sizes; (void)n_in; (void)out_size;

    const float* in = (const float*)d_in[0];
    float* out = (float*)d_out;

    const dim3 gemm_grid(C_DIM / BN, S_TOT / BM);   // (4, 64)
    const int EW_BLOCKS = S_TOT * C_DIM / 256;      // 16384
    const int WC_BLOCKS = 27 * C_DIM * C_DIM / 256; // 27648
    const dim3 tb(32, 8);

    // input NCDHW [512][8192] -> channels-last g_X[8192][512]
    transpose_k<<<dim3(S_TOT / 32, C_DIM / 32), tb>>>(in, -1, nullptr, 0, C_DIM, S_TOT);

    auto resnet = [&](int base) {
        const float* n1s = (const float*)d_in[base + 0];
        const float* n1b = (const float*)d_in[base + 1];
        const float* w1  = (const float*)d_in[base + 2];
        const float* b1  = (const float*)d_in[base + 3];
        const float* n2s = (const float*)d_in[base + 4];
        const float* n2b = (const float*)d_in[base + 5];
        const float* w2  = (const float*)d_in[base + 6];
        const float* b2  = (const float*)d_in[base + 7];

        gn_stats<<<NG, 256>>>(0);
        gn_apply<<<EW_BLOCKS, 256>>>(0, n1s, n1b, 1);
        wconv_tr<<<WC_BLOCKS, 256>>>(w1);
        gemm_nn<1><<<gemm_grid, 256>>>(1, 8, b1, -1, 2, C_DIM, 27 * C_DIM, C_DIM, C_DIM);
        gn_stats<<<NG, 256>>>(2);
        gn_apply<<<EW_BLOCKS, 256>>>(2, n2s, n2b, 1);
        wconv_tr<<<WC_BLOCKS, 256>>>(w2);
        gemm_nn<1><<<gemm_grid, 256>>>(1, 8, b2, 0, 0, C_DIM, 27 * C_DIM, C_DIM, C_DIM);
    };

    // ---- resnet block 0 (inputs 1..8) ----
    resnet(1);

    // ---- causal frame attention (inputs 17..26) ----
    {
        const float* gns = (const float*)d_in[17];
        const float* gnb = (const float*)d_in[18];
        const float* wq  = (const float*)d_in[19];
        const float* bq  = (const float*)d_in[20];
        const float* wk  = (const float*)d_in[21];
        const float* bk  = (const float*)d_in[22];
        const float* wv  = (const float*)d_in[23];
        const float* bv  = (const float*)d_in[24];
        const float* wo  = (const float*)d_in[25];
        const float* bo  = (const float*)d_in[26];

        gn_stats<<<NG, 256>>>(0);
        gn_apply<<<EW_BLOCKS, 256>>>(0, gns, gnb, 0);

        const dim3 wl_grid(C_DIM / 32, C_DIM / 32);
        transpose_k<<<wl_grid, tb>>>(wq, -1, nullptr, 9, C_DIM, C_DIM);
        gemm_nn<0><<<gemm_grid, 256>>>(1, 9, bq, -1, 3, C_DIM, C_DIM, C_DIM, C_DIM);
        transpose_k<<<wl_grid, tb>>>(wk, -1, nullptr, 9, C_DIM, C_DIM);
        gemm_nn<0><<<gemm_grid, 256>>>(1, 9, bk, -1, 4, C_DIM, C_DIM, C_DIM, C_DIM);
        transpose_k<<<wl_grid, tb>>>(wv, -1, nullptr, 9, C_DIM, C_DIM);
        gemm_nn<0><<<gemm_grid, 256>>>(1, 9, bv, -1, 5, C_DIM, C_DIM, C_DIM, C_DIM);

        const float scale = 0.044194173824159216f;  // 512^-0.5
        gemm_nt_scores<<<dim3(S_TOT / BN, S_TOT / BM), 256>>>(scale);
        softmax_rows<<<S_TOT, 256>>>();
        gemm_nn<2><<<gemm_grid, 256>>>(7, 5, nullptr, -1, 6, C_DIM, S_TOT, S_TOT, C_DIM);

        transpose_k<<<wl_grid, tb>>>(wo, -1, nullptr, 9, C_DIM, C_DIM);
        gemm_nn<0><<<gemm_grid, 256>>>(6, 9, bo, 0, 0, C_DIM, C_DIM, C_DIM, C_DIM);
    }

    // ---- resnet block 1 (inputs 9..16) ----
    resnet(9);

    // channels-last g_X[8192][512] -> NCDHW out [512][8192]
    transpose_k<<<dim3(C_DIM / 32, S_TOT / 32), tb>>>(nullptr, 0, out, -1, S_TOT, C_DIM);
}

// round 5
// speedup vs baseline: 2.4013x; 2.4013x over previous
#include <cuda_runtime.h>
#include <math.h>
#include <stdint.h>

// ---------------------------------------------------------------------------
// UNetMidBlockCausal3D: resnet -> causal frame attention -> resnet
// B=1, C=512, T=8, H=32, W=32  => S = 8192 positions, 32 groups of 16 chans.
// Channels-last internally: A[s, c].  All big GEMMs run on TF32 tensor cores
// (mma.sync.m16n8k8, fp32 accumulate); every MMA operand is pre-rounded to
// TF32 (cvt.rna) at its producer so in-MMA truncation is exact.
// ---------------------------------------------------------------------------

#define S_TOT 8192
#define C_DIM 512
#define NG    32
#define GSZ   16

#define BM 128
#define BN 128
#define BK 16
#define SROW 20   // smem row stride (floats) for [row][k-perm] tiles

// Scratch (device globals; runtime allocation is forbidden)
__device__ float g_X[S_TOT * C_DIM];          // 0: residual stream (fp32)
__device__ float g_N[S_TOT * C_DIM];          // 1: normalized (tf32-rounded)
__device__ float g_H[S_TOT * C_DIM];          // 2: conv intermediate / Vt
__device__ float g_Q[S_TOT * C_DIM];          // 3 (tf32)
__device__ float g_K[S_TOT * C_DIM];          // 4 (tf32)
__device__ float g_V[S_TOT * C_DIM];          // 5 (tf32)
__device__ float g_O[S_TOT * C_DIM];          // 6 (tf32)
__device__ float g_S[(size_t)S_TOT * S_TOT];  // 7: scores / exp (256 MB)
__device__ float g_Wc[27 * C_DIM * C_DIM];    // 8: conv W [tap][co][ci] (tf32)
__device__ float g_Wl[C_DIM * C_DIM];         // 9: linear W [o][c] (tf32)
__device__ float g_mu[NG];
__device__ float g_rs[NG];
__device__ float g_inv[S_TOT];                // per-row 1/sum(exp)

__device__ __forceinline__ float* BUF(int id) {
    switch (id) {
        case 0: return g_X;  case 1: return g_N;  case 2: return g_H;
        case 3: return g_Q;  case 4: return g_K;  case 5: return g_V;
        case 6: return g_O;  case 7: return g_S;  case 8: return g_Wc;
        default: return g_Wl;
    }
}

__device__ __forceinline__ float tf32r(float x) {
    uint32_t o;
    asm("cvt.rna.tf32.f32 %0, %1;" : "=r"(o) : "f"(x));
    return __uint_as_float(o);
}

// D += A(16x8) * B(8x8), tf32 row.col.  a-lo holds {a0,a2} (row r), a-hi {a1,a3}.
__device__ __forceinline__ void mma8(float* c, float2 alo, float2 ahi, float2 b) {
    asm volatile(
        "mma.sync.aligned.m16n8k8.row.col.f32.tf32.tf32.f32 "
        "{%0,%1,%2,%3}, {%4,%5,%6,%7}, {%8,%9}, {%0,%1,%2,%3};\n"
        : "+f"(c[0]), "+f"(c[1]), "+f"(c[2]), "+f"(c[3])
        : "r"(__float_as_uint(alo.x)), "r"(__float_as_uint(ahi.x)),
          "r"(__float_as_uint(alo.y)), "r"(__float_as_uint(ahi.y)),
          "r"(__float_as_uint(b.x)),   "r"(__float_as_uint(b.y)));
}

// ---------------------------------------------------------------------------
// 32x32-tiled transpose: dst[c][r] = src[r][c].  src is rows x cols.
// ---------------------------------------------------------------------------
__global__ void transpose_k(const float* src_ext, int src_id,
                            float* dst_ext, int dst_id,
                            int rows, int cols) {
    const float* src = src_ext ? src_ext : BUF(src_id);
    float* dst = dst_ext ? dst_ext : BUF(dst_id);
    __shared__ float tile[32][33];
    int c0 = blockIdx.x * 32, r0 = blockIdx.y * 32;
    int c = c0 + threadIdx.x;
    #pragma unroll
    for (int j = threadIdx.y; j < 32; j += 8)
        tile[j][threadIdx.x] = src[(size_t)(r0 + j) * cols + c];
    __syncthreads();
    int r2 = r0 + threadIdx.x;
    #pragma unroll
    for (int j = threadIdx.y; j < 32; j += 8)
        dst[(size_t)(c0 + j) * rows + r2] = tile[threadIdx.x][j];
}

// Conv weight prep: g_Wc[tap][co][ci] = tf32(w[co][ci][tap])
__global__ void wconv_tr(const float* __restrict__ w) {
    int idx = blockIdx.x * 256 + threadIdx.x;
    int tap = idx >> 18;
    int rem = idx & 262143;
    int co  = rem >> 9;
    int ci  = rem & 511;
    g_Wc[idx] = tf32r(w[(size_t)co * (C_DIM * 27) + ci * 27 + tap]);
}

// Linear weight prep: g_Wl = tf32(w), layout already [o][c] = [n][k]
__global__ void round_copy(const float* __restrict__ w) {
    int idx = blockIdx.x * 256 + threadIdx.x;
    g_Wl[idx] = tf32r(w[idx]);
}

// ---------------------------------------------------------------------------
// GroupNorm stats: one block (1024 thr) per group; channels-last A[s, c].
// ---------------------------------------------------------------------------
__global__ void gn_stats(int aid) {
    const float* A = BUF(aid);
    __shared__ float sh[1024], sh2[1024];
    int g = blockIdx.x, tid = threadIdx.x;
    const float* base = A + g * GSZ;
    float s = 0.f, ss = 0.f;
    for (int idx = tid; idx < S_TOT * GSZ; idx += 1024) {
        int r = idx >> 4, c = idx & 15;
        float v = base[(size_t)r * C_DIM + c];
        s += v; ss += v * v;
    }
    sh[tid] = s; sh2[tid] = ss;
    __syncthreads();
    for (int o = 512; o > 0; o >>= 1) {
        if (tid < o) { sh[tid] += sh[tid + o]; sh2[tid] += sh2[tid + o]; }
        __syncthreads();
    }
    if (tid == 0) {
        const float invn = 1.f / (float)(S_TOT * GSZ);
        float m   = sh[0] * invn;
        float var = sh2[0] * invn - m * m;
        g_mu[g] = m;
        g_rs[g] = rsqrtf(var + 1e-6f);
    }
}

// GroupNorm apply (+ optional SiLU); writes g_N tf32-rounded.
__global__ void gn_apply(int aid, const float* __restrict__ sc,
                         const float* __restrict__ bi, int do_silu) {
    const float* A = BUF(aid);
    int idx = blockIdx.x * 256 + threadIdx.x;
    float v = A[idx];
    int c = idx & 511;
    int g = c >> 4;
    float y = (v - g_mu[g]) * g_rs[g] * sc[c] + bi[c];
    if (do_silu) y = y * (1.f / (1.f + __expf(-y)));
    g_N[idx] = tf32r(y);
}

// ---------------------------------------------------------------------------
// TF32 tensor-core GEMM: C[m,n] = sum_k A[m,k]*B[n,k]  (B is [n][k] row-major)
//   MODE 0: linear (K=512).
//   MODE 1: conv (K=27*512): A rows gathered via srow; B = g_Wc [tap][n][kloc].
//   MODE 2: scores: causal tile skip; epilogue *scale; C = g_S (ldc 8192).
//   MODE 3: PV: K limited to causal prefix; epilogue *g_inv[row].
// 128x128x16 tile, 8 warps (4m x 2n), warp tile 32x64, double-buffered smem
// with k-permuted layout so fragments load as single LDS.64.
// ---------------------------------------------------------------------------
template <int MODE>
__global__ __launch_bounds__(256)
void mma_gemm(int aid, const float* Bext, int bid, const float* __restrict__ bias,
              int rid, int cid, int Ktot, int lda, int ldb, int ldc,
              float scale, int do_round) {
    const float* A  = BUF(aid);
    const float* Bm = Bext ? Bext : BUF(bid);
    const float* resid = (rid >= 0) ? BUF(rid) : nullptr;
    float* C = BUF(cid);

    const int m0 = blockIdx.y * BM;
    const int n0 = blockIdx.x * BN;
    if (MODE == 2 && n0 >= (((m0 >> 10) + 1) << 10)) return;

    __shared__ __align__(16) float As[2][BM][SROW];
    __shared__ __align__(16) float Bs[2][BN][SROW];
    __shared__ short srow[(MODE == 1) ? 27 : 1][BM];

    const int tid  = threadIdx.x;
    const int lane = tid & 31;
    const int warp = tid >> 5;
    const int wm = warp >> 1;   // 0..3 -> m offset wm*32
    const int wn = warp & 1;    // 0..1 -> n offset wn*64
    const int fr = lane >> 2;   // 0..7
    const int fc = lane & 3;    // 0..3

    if (MODE == 1) {
        for (int i = tid; i < 27 * BM; i += 256) {
            int tap = i >> 7, r = i & 127;
            int s = m0 + r;
            int t = s >> 10, h = (s >> 5) & 31, w = s & 31;
            int kd = tap / 9, kh = (tap / 3) % 3, kw = tap % 3;
            int tt = t + kd - 2; if (tt < 0) tt = 0;
            int hh = h + kh - 1; hh = hh < 0 ? 0 : (hh > 31 ? 31 : hh);
            int ww = w + kw - 1; ww = ww < 0 ? 0 : (ww > 31 ? 31 : ww);
            srow[tap][r] = (short)((tt << 10) | (hh << 5) | ww);
        }
        __syncthreads();
    }

    int Keff = Ktot;
    if (MODE == 3) Keff = ((m0 >> 10) + 1) << 10;
    const int nkt = Keff / BK;

    float acc[2][8][4];
    #pragma unroll
    for (int mi = 0; mi < 2; mi++)
        #pragma unroll
        for (int ni = 0; ni < 8; ni++)
            #pragma unroll
            for (int r = 0; r < 4; r++) acc[mi][ni][r] = 0.f;

    float4 pa[2], pb[2];

    auto fetch = [&](int kt) {
        const int kk = kt * BK;
        #pragma unroll
        for (int it = 0; it < 2; it++) {
            int f4 = tid + it * 256;
            int row = f4 >> 2, c4 = f4 & 3;
            int arow, kq;
            if (MODE == 1) { arow = srow[kk >> 9][row]; kq = (kk & 511) + c4 * 4; }
            else           { arow = m0 + row;           kq = kk + c4 * 4; }
            pa[it] = *(const float4*)(A + (size_t)arow * lda + kq);
            const float* bp;
            if (MODE == 1)
                bp = Bm + ((size_t)(kk >> 9)) * (C_DIM * C_DIM)
                        + (size_t)(n0 + row) * C_DIM + (kk & 511) + c4 * 4;
            else
                bp = Bm + (size_t)(n0 + row) * ldb + kk + c4 * 4;
            pb[it] = *(const float4*)bp;
        }
    };
    // k-permuted store: k = c4*4 + j  ->  pos = (c4>>1)*8 + 2*j + (c4&1)
    auto stage = [&](int b) {
        #pragma unroll
        for (int it = 0; it < 2; it++) {
            int f4 = tid + it * 256;
            int row = f4 >> 2, c4 = f4 & 3;
            int base = ((c4 >> 1) << 3) + (c4 & 1);
            float* d = &As[b][row][base];
            d[0] = pa[it].x; d[2] = pa[it].y; d[4] = pa[it].z; d[6] = pa[it].w;
            float* e = &Bs[b][row][base];
            e[0] = pb[it].x; e[2] = pb[it].y; e[4] = pb[it].z; e[6] = pb[it].w;
        }
    };
    auto compute = [&](int s) {
        #pragma unroll
        for (int g = 0; g < 2; g++) {
            float2 bf[8];
            #pragma unroll
            for (int ni = 0; ni < 8; ni++)
                bf[ni] = *(const float2*)&Bs[s][wn * 64 + ni * 8 + fr][g * 8 + 2 * fc];
            float2 alo[2], ahi[2];
            #pragma unroll
            for (int mi = 0; mi < 2; mi++) {
                alo[mi] = *(const float2*)&As[s][wm * 32 + mi * 16 + fr][g * 8 + 2 * fc];
                ahi[mi] = *(const float2*)&As[s][wm * 32 + mi * 16 + fr + 8][g * 8 + 2 * fc];
            }
            #pragma unroll
            for (int mi = 0; mi < 2; mi++)
                #pragma unroll
                for (int ni = 0; ni < 8; ni++)
                    mma8(acc[mi][ni], alo[mi], ahi[mi], bf[ni]);
        }
    };

    fetch(0);
    stage(0);
    __syncthreads();
    int cur = 0;
    for (int kt = 0; kt < nkt; kt++) {
        if (kt + 1 < nkt) fetch(kt + 1);
        compute(cur);
        if (kt + 1 < nkt) {
            stage(cur ^ 1);
            __syncthreads();
            cur ^= 1;
        }
    }

    // Epilogue: c0,c1 -> row fr, cols 2fc,2fc+1; c2,c3 -> row fr+8.
    #pragma unroll
    for (int mi = 0; mi < 2; mi++) {
        #pragma unroll
        for (int h = 0; h < 2; h++) {
            int row = m0 + wm * 32 + mi * 16 + h * 8 + fr;
            float rsc = (MODE == 3) ? g_inv[row] : scale;
            #pragma unroll
            for (int ni = 0; ni < 8; ni++) {
                int col = n0 + wn * 64 + ni * 8 + 2 * fc;
                float v0 = acc[mi][ni][h * 2 + 0] * rsc;
                float v1 = acc[mi][ni][h * 2 + 1] * rsc;
                if (bias) { v0 += bias[col]; v1 += bias[col + 1]; }
                if (resid) {
                    float2 r = *(const float2*)(resid + (size_t)row * ldc + col);
                    v0 += r.x; v1 += r.y;
                }
                if (do_round) { v0 = tf32r(v0); v1 = tf32r(v1); }
                float2 o; o.x = v0; o.y = v1;
                *(float2*)(C + (size_t)row * ldc + col) = o;
            }
        }
    }
}

// ---------------------------------------------------------------------------
// Softmax over causal prefix L = (frame+1)*1024.  Stores tf32-rounded,
// UNNORMALIZED exp in g_S; 1/sum in g_inv (PV epilogue applies it).
// ---------------------------------------------------------------------------
__global__ void softmax_rows() {
    const int q = blockIdx.x;
    const int L = ((q >> 10) + 1) << 10;
    float* row = g_S + (size_t)q * S_TOT;
    __shared__ float red[256];
    const int tid = threadIdx.x;

    float m = -1e30f;
    for (int i = tid; i < L; i += 256) m = fmaxf(m, row[i]);
    red[tid] = m; __syncthreads();
    for (int o = 128; o > 0; o >>= 1) {
        if (tid < o) red[tid] = fmaxf(red[tid], red[tid + o]);
        __syncthreads();
    }
    m = red[0];
    __syncthreads();

    float s = 0.f;
    for (int i = tid; i < L; i += 256) {
        float e = tf32r(__expf(row[i] - m));
        row[i] = e;
        s += e;
    }
    red[tid] = s; __syncthreads();
    for (int o = 128; o > 0; o >>= 1) {
        if (tid < o) red[tid] += red[tid + o];
        __syncthreads();
    }
    if (tid == 0) g_inv[q] = 1.f / red[0];
}

// ---------------------------------------------------------------------------
// Host orchestration — kernel launches only (graph-capture safe).
// ---------------------------------------------------------------------------
extern "C" void kernel_launch(void* const* d_in, const int* in_sizes, int n_in,
                              void* d_out, int out_size) {
    (void)in_sizes; (void)n_in; (void)out_size;

    const float* in = (const float*)d_in[0];
    float* out = (float*)d_out;

    const dim3 gemm_grid(C_DIM / BN, S_TOT / BM);   // (4, 64)
    const int EW_BLOCKS = S_TOT * C_DIM / 256;      // 16384
    const int WC_BLOCKS = 27 * C_DIM * C_DIM / 256; // 27648
    const int WL_BLOCKS = C_DIM * C_DIM / 256;      // 1024
    const dim3 tb(32, 8);

    // input NCDHW [512][8192] -> channels-last g_X[8192][512]
    transpose_k<<<dim3(S_TOT / 32, C_DIM / 32), tb>>>(in, -1, nullptr, 0, C_DIM, S_TOT);

    auto resnet = [&](int base) {
        const float* n1s = (const float*)d_in[base + 0];
        const float* n1b = (const float*)d_in[base + 1];
        const float* w1  = (const float*)d_in[base + 2];
        const float* b1  = (const float*)d_in[base + 3];
        const float* n2s = (const float*)d_in[base + 4];
        const float* n2b = (const float*)d_in[base + 5];
        const float* w2  = (const float*)d_in[base + 6];
        const float* b2  = (const float*)d_in[base + 7];

        gn_stats<<<NG, 1024>>>(0);
        gn_apply<<<EW_BLOCKS, 256>>>(0, n1s, n1b, 1);
        wconv_tr<<<WC_BLOCKS, 256>>>(w1);
        mma_gemm<1><<<gemm_grid, 256>>>(1, nullptr, 8, b1, -1, 2,
                                        27 * C_DIM, C_DIM, C_DIM, C_DIM, 1.f, 0);
        gn_stats<<<NG, 1024>>>(2);
        gn_apply<<<EW_BLOCKS, 256>>>(2, n2s, n2b, 1);
        wconv_tr<<<WC_BLOCKS, 256>>>(w2);
        mma_gemm<1><<<gemm_grid, 256>>>(1, nullptr, 8, b2, 0, 0,
                                        27 * C_DIM, C_DIM, C_DIM, C_DIM, 1.f, 0);
    };

    // ---- resnet block 0 (inputs 1..8) ----
    resnet(1);

    // ---- causal frame attention (inputs 17..26) ----
    {
        const float* gns = (const float*)d_in[17];
        const float* gnb = (const float*)d_in[18];
        const float* wq  = (const float*)d_in[19];
        const float* bq  = (const float*)d_in[20];
        const float* wk  = (const float*)d_in[21];
        const float* bk  = (const float*)d_in[22];
        const float* wv  = (const float*)d_in[23];
        const float* bv  = (const float*)d_in[24];
        const float* wo  = (const float*)d_in[25];
        const float* bo  = (const float*)d_in[26];

        gn_stats<<<NG, 1024>>>(0);
        gn_apply<<<EW_BLOCKS, 256>>>(0, gns, gnb, 0);

        round_copy<<<WL_BLOCKS, 256>>>(wq);
        mma_gemm<0><<<gemm_grid, 256>>>(1, nullptr, 9, bq, -1, 3,
                                        C_DIM, C_DIM, C_DIM, C_DIM, 1.f, 1);
        round_copy<<<WL_BLOCKS, 256>>>(wk);
        mma_gemm<0><<<gemm_grid, 256>>>(1, nullptr, 9, bk, -1, 4,
                                        C_DIM, C_DIM, C_DIM, C_DIM, 1.f, 1);
        round_copy<<<WL_BLOCKS, 256>>>(wv);
        mma_gemm<0><<<gemm_grid, 256>>>(1, nullptr, 9, bv, -1, 5,
                                        C_DIM, C_DIM, C_DIM, C_DIM, 1.f, 1);

        // scores: S[q,k] = scale * Q.K^T  (block-causal skip)
        const float scale = 0.044194173824159216f;  // 512^-0.5
        mma_gemm<2><<<dim3(S_TOT / BN, S_TOT / BM), 256>>>(
            3, nullptr, 4, nullptr, -1, 7, C_DIM, C_DIM, C_DIM, S_TOT, scale, 0);
        softmax_rows<<<S_TOT, 256>>>();

        // Vt = V^T into g_H (tf32 values preserved)
        transpose_k<<<dim3(C_DIM / 32, S_TOT / 32), tb>>>(nullptr, 5, nullptr, 2,
                                                          S_TOT, C_DIM);
        // O = P @ V  (A = exp scores, B = Vt [c][s]); epilogue * g_inv, round
        mma_gemm<3><<<gemm_grid, 256>>>(7, nullptr, 2, nullptr, -1, 6,
                                        S_TOT, S_TOT, S_TOT, C_DIM, 1.f, 1);

        round_copy<<<WL_BLOCKS, 256>>>(wo);
        mma_gemm<0><<<gemm_grid, 256>>>(6, nullptr, 9, bo, 0, 0,
                                        C_DIM, C_DIM, C_DIM, C_DIM, 1.f, 0);
    }

    // ---- resnet block 1 (inputs 9..16) ----
    resnet(9);

    // channels-last g_X[8192][512] -> NCDHW out [512][8192]
    transpose_k<<<dim3(C_DIM / 32, S_TOT / 32), tb>>>(nullptr, 0, out, -1, S_TOT, C_DIM);
}

// round 6
// speedup vs baseline: 3.3248x; 1.3846x over previous
#include <cuda_runtime.h>
#include <math.h>
#include <stdint.h>

// ---------------------------------------------------------------------------
// UNetMidBlockCausal3D: resnet -> causal frame attention -> resnet
// B=1, C=512, T=8, H=32, W=32  => S = 8192 positions, 32 groups of 16 chans.
// Channels-last internally: A[s, c].  All big GEMMs run on TF32 tensor cores
// (mma.sync.m16n8k8, fp32 accumulate) fed by cp.async double-buffered smem.
// Within each k8 mma group, mma k-positions (fc, fc+4) carry logical ks
// (2fc, 2fc+1) consistently for A and B, so plain [row][k] smem tiles give
// single-LDS.64 fragments with no layout permutation.
// ---------------------------------------------------------------------------

#define S_TOT 8192
#define C_DIM 512
#define NG    32
#define GSZ   16

#define BM 128
#define BN 128
#define BK 16
#define RPAD 24            // smem row stride (floats): conflict-free LDS.64
#define STG_BYTES (BM * RPAD * 4)   // 12288 per tile per stage

// Scratch (device globals; runtime allocation is forbidden)
__device__ float g_X[S_TOT * C_DIM];          // 0: residual stream (fp32)
__device__ float g_N[S_TOT * C_DIM];          // 1: normalized (tf32-rounded)
__device__ float g_H[S_TOT * C_DIM];          // 2: conv intermediate / Vt
__device__ float g_Q[S_TOT * C_DIM];          // 3 (tf32)
__device__ float g_K[S_TOT * C_DIM];          // 4 (tf32)
__device__ float g_V[S_TOT * C_DIM];          // 5 (tf32)
__device__ float g_O[S_TOT * C_DIM];          // 6 (tf32)
__device__ float g_S[(size_t)S_TOT * S_TOT];  // 7: scores / exp (256 MB)
__device__ float g_Wc[27 * C_DIM * C_DIM];    // 8: conv W [tap][co][ci] (tf32)
__device__ float g_Wl[C_DIM * C_DIM];         // 9: linear W [o][c] (tf32)
__device__ float g_mu[NG];
__device__ float g_rs[NG];
__device__ float g_inv[S_TOT];                // per-row 1/sum(exp)

__device__ __forceinline__ float* BUF(int id) {
    switch (id) {
        case 0: return g_X;  case 1: return g_N;  case 2: return g_H;
        case 3: return g_Q;  case 4: return g_K;  case 5: return g_V;
        case 6: return g_O;  case 7: return g_S;  case 8: return g_Wc;
        default: return g_Wl;
    }
}

__device__ __forceinline__ float tf32r(float x) {
    uint32_t o;
    asm("cvt.rna.tf32.f32 %0, %1;" : "=r"(o) : "f"(x));
    return __uint_as_float(o);
}

// D += A(16x8) * B(8x8), tf32 row.col.
__device__ __forceinline__ void mma8(float* c, float2 alo, float2 ahi, float2 b) {
    asm volatile(
        "mma.sync.aligned.m16n8k8.row.col.f32.tf32.tf32.f32 "
        "{%0,%1,%2,%3}, {%4,%5,%6,%7}, {%8,%9}, {%0,%1,%2,%3};\n"
        : "+f"(c[0]), "+f"(c[1]), "+f"(c[2]), "+f"(c[3])
        : "r"(__float_as_uint(alo.x)), "r"(__float_as_uint(ahi.x)),
          "r"(__float_as_uint(alo.y)), "r"(__float_as_uint(ahi.y)),
          "r"(__float_as_uint(b.x)),   "r"(__float_as_uint(b.y)));
}

__device__ __forceinline__ void cpa16(uint32_t dst, const void* src) {
    asm volatile("cp.async.cg.shared.global [%0], [%1], 16;\n"
                 :: "r"(dst), "l"(src));
}
#define CP_COMMIT() asm volatile("cp.async.commit_group;\n" ::: "memory")
#define CP_WAIT1()  asm volatile("cp.async.wait_group 1;\n" ::: "memory")

// ---------------------------------------------------------------------------
// 32x32-tiled transpose: dst[c][r] = src[r][c].  src is rows x cols.
// ---------------------------------------------------------------------------
__global__ void transpose_k(const float* src_ext, int src_id,
                            float* dst_ext, int dst_id,
                            int rows, int cols) {
    const float* src = src_ext ? src_ext : BUF(src_id);
    float* dst = dst_ext ? dst_ext : BUF(dst_id);
    __shared__ float tile[32][33];
    int c0 = blockIdx.x * 32, r0 = blockIdx.y * 32;
    int c = c0 + threadIdx.x;
    #pragma unroll
    for (int j = threadIdx.y; j < 32; j += 8)
        tile[j][threadIdx.x] = src[(size_t)(r0 + j) * cols + c];
    __syncthreads();
    int r2 = r0 + threadIdx.x;
    #pragma unroll
    for (int j = threadIdx.y; j < 32; j += 8)
        dst[(size_t)(c0 + j) * rows + r2] = tile[threadIdx.x][j];
}

// Conv weight prep: g_Wc[tap][co][ci] = tf32(w[co][ci][tap])
__global__ void wconv_tr(const float* __restrict__ w) {
    int idx = blockIdx.x * 256 + threadIdx.x;
    int tap = idx >> 18;
    int rem = idx & 262143;
    int co  = rem >> 9;
    int ci  = rem & 511;
    g_Wc[idx] = tf32r(w[(size_t)co * (C_DIM * 27) + ci * 27 + tap]);
}

// Linear weight prep: g_Wl = tf32(w), layout already [o][c] = [n][k]
__global__ void round_copy(const float* __restrict__ w) {
    int idx = blockIdx.x * 256 + threadIdx.x;
    g_Wl[idx] = tf32r(w[idx]);
}

// ---------------------------------------------------------------------------
// GroupNorm stats: one block (1024 thr) per group; channels-last A[s, c].
// ---------------------------------------------------------------------------
__global__ void gn_stats(int aid) {
    const float* A = BUF(aid);
    __shared__ float sh[1024], sh2[1024];
    int g = blockIdx.x, tid = threadIdx.x;
    const float* base = A + g * GSZ;
    float s = 0.f, ss = 0.f;
    for (int idx = tid; idx < S_TOT * GSZ; idx += 1024) {
        int r = idx >> 4, c = idx & 15;
        float v = base[(size_t)r * C_DIM + c];
        s += v; ss += v * v;
    }
    sh[tid] = s; sh2[tid] = ss;
    __syncthreads();
    for (int o = 512; o > 0; o >>= 1) {
        if (tid < o) { sh[tid] += sh[tid + o]; sh2[tid] += sh2[tid + o]; }
        __syncthreads();
    }
    if (tid == 0) {
        const float invn = 1.f / (float)(S_TOT * GSZ);
        float m   = sh[0] * invn;
        float var = sh2[0] * invn - m * m;
        g_mu[g] = m;
        g_rs[g] = rsqrtf(var + 1e-6f);
    }
}

// GroupNorm apply (+ optional SiLU); writes g_N tf32-rounded.
__global__ void gn_apply(int aid, const float* __restrict__ sc,
                         const float* __restrict__ bi, int do_silu) {
    const float* A = BUF(aid);
    int idx = blockIdx.x * 256 + threadIdx.x;
    float v = A[idx];
    int c = idx & 511;
    int g = c >> 4;
    float y = (v - g_mu[g]) * g_rs[g] * sc[c] + bi[c];
    if (do_silu) y = y * (1.f / (1.f + __expf(-y)));
    g_N[idx] = tf32r(y);
}

// ---------------------------------------------------------------------------
// TF32 tensor-core GEMM: C[m,n] = sum_k A[m,k]*B[n,k]  (B is [n][k] row-major)
//   MODE 0: linear (K=512).
//   MODE 1: conv (K=27*512): A rows gathered via inline tap/clamp arithmetic;
//           B = g_Wc [tap][n][kloc].
//   MODE 2: scores: causal tile skip; epilogue *scale; C = g_S (ldc 8192).
//   MODE 3: PV: K limited to causal prefix; epilogue *g_inv[row].
// 128x128x16 tile, 8 warps (4m x 2n), warp tile 32x64, cp.async 2-stage.
// ---------------------------------------------------------------------------
template <int MODE>
__global__ __launch_bounds__(256, 2)
void mma_gemm(int aid, int bid, const float* __restrict__ bias,
              int rid, int cid, int Ktot, int lda, int ldb, int ldc,
              float scale, int do_round) {
    const float* A  = BUF(aid);
    const float* Bm = BUF(bid);
    const float* resid = (rid >= 0) ? BUF(rid) : nullptr;
    float* C = BUF(cid);

    const int m0 = blockIdx.y * BM;
    const int n0 = blockIdx.x * BN;
    if (MODE == 2 && n0 >= (((m0 >> 10) + 1) << 10)) return;

    __shared__ __align__(16) float As[2][BM][RPAD];   // 24576 B
    __shared__ __align__(16) float Bs[2][BN][RPAD];   // 24576 B  (total 48 KB)

    const int tid  = threadIdx.x;
    const int lane = tid & 31;
    const int warp = tid >> 5;
    const int wm = warp >> 1;   // m offset wm*32
    const int wn = warp & 1;    // n offset wn*64
    const int fr = lane >> 2;   // 0..7
    const int fc = lane & 3;    // 0..3

    int Keff = Ktot;
    if (MODE == 3) Keff = ((m0 >> 10) + 1) << 10;
    const int nkt = Keff / BK;

    // ---- per-thread fetch precomputation (2 x 16B per operand per stage) ----
    const float* aptr[2];   // MODE != 1: full row ptr (add kk per stage)
    const float* bptr[2];   // MODE != 1: full row ptr; MODE 1: row base
    int tv[2], hv[2], wv[2], koff[2];
    uint32_t sA[2], sB[2];
    #pragma unroll
    for (int it = 0; it < 2; it++) {
        int f4 = tid + it * 256;
        int row = f4 >> 2, c4 = f4 & 3;
        koff[it] = c4 * 4;
        if (MODE == 1) {
            int s = m0 + row;
            tv[it] = s >> 10; hv[it] = (s >> 5) & 31; wv[it] = s & 31;
            bptr[it] = Bm + (size_t)(n0 + row) * C_DIM + koff[it];
        } else {
            aptr[it] = A + (size_t)(m0 + row) * lda + koff[it];
            bptr[it] = Bm + (size_t)(n0 + row) * ldb + koff[it];
        }
        sA[it] = (uint32_t)__cvta_generic_to_shared(&As[0][row][koff[it]]);
        sB[it] = (uint32_t)__cvta_generic_to_shared(&Bs[0][row][koff[it]]);
    }

    auto fetch = [&](int kt, int b) {
        const int kk = kt * BK;
        const uint32_t off = (uint32_t)b * STG_BYTES;
        if (MODE == 1) {
            const int tap  = kk >> 9;
            const int kloc = kk & 511;
            const int kd = tap / 9;
            const int r9 = tap - kd * 9;
            const int kh = r9 / 3;
            const int kw = r9 - kh * 3;
            #pragma unroll
            for (int it = 0; it < 2; it++) {
                int tt = tv[it] + kd - 2; if (tt < 0) tt = 0;
                int hh = hv[it] + kh - 1; hh = hh < 0 ? 0 : (hh > 31 ? 31 : hh);
                int ww = wv[it] + kw - 1; ww = ww < 0 ? 0 : (ww > 31 ? 31 : ww);
                int arow = (tt << 10) | (hh << 5) | ww;
                cpa16(sA[it] + off, A + (size_t)arow * C_DIM + kloc + koff[it]);
                cpa16(sB[it] + off, bptr[it] + (size_t)tap * (C_DIM * C_DIM) + kloc);
            }
        } else {
            #pragma unroll
            for (int it = 0; it < 2; it++) {
                cpa16(sA[it] + off, aptr[it] + kk);
                cpa16(sB[it] + off, bptr[it] + kk);
            }
        }
    };

    float acc[2][8][4];
    #pragma unroll
    for (int mi = 0; mi < 2; mi++)
        #pragma unroll
        for (int ni = 0; ni < 8; ni++)
            #pragma unroll
            for (int r = 0; r < 4; r++) acc[mi][ni][r] = 0.f;

    auto compute = [&](int s) {
        #pragma unroll
        for (int g = 0; g < 2; g++) {
            float2 bf[8];
            #pragma unroll
            for (int ni = 0; ni < 8; ni++)
                bf[ni] = *(const float2*)&Bs[s][wn * 64 + ni * 8 + fr][g * 8 + 2 * fc];
            float2 alo[2], ahi[2];
            #pragma unroll
            for (int mi = 0; mi < 2; mi++) {
                alo[mi] = *(const float2*)&As[s][wm * 32 + mi * 16 + fr][g * 8 + 2 * fc];
                ahi[mi] = *(const float2*)&As[s][wm * 32 + mi * 16 + fr + 8][g * 8 + 2 * fc];
            }
            #pragma unroll
            for (int mi = 0; mi < 2; mi++)
                #pragma unroll
                for (int ni = 0; ni < 8; ni++)
                    mma8(acc[mi][ni], alo[mi], ahi[mi], bf[ni]);
        }
    };

    // ---- prologue: 2 stages in flight ----
    fetch(0, 0); CP_COMMIT();
    fetch(1, 1); CP_COMMIT();
    CP_WAIT1();
    __syncthreads();

    int cur = 0;
    for (int kt = 0; kt < nkt; kt++) {
        compute(cur);
        if (kt + 1 < nkt) {
            __syncthreads();                 // everyone done reading buf cur
            if (kt + 2 < nkt) fetch(kt + 2, cur);
            CP_COMMIT();
            CP_WAIT1();                      // stage kt+1 landed
            __syncthreads();
            cur ^= 1;
        }
    }

    // Epilogue: c0,c1 -> row fr, cols 2fc,2fc+1; c2,c3 -> row fr+8.
    #pragma unroll
    for (int mi = 0; mi < 2; mi++) {
        #pragma unroll
        for (int h = 0; h < 2; h++) {
            int row = m0 + wm * 32 + mi * 16 + h * 8 + fr;
            float rsc = (MODE == 3) ? g_inv[row] : scale;
            #pragma unroll
            for (int ni = 0; ni < 8; ni++) {
                int col = n0 + wn * 64 + ni * 8 + 2 * fc;
                float v0 = acc[mi][ni][h * 2 + 0] * rsc;
                float v1 = acc[mi][ni][h * 2 + 1] * rsc;
                if (bias) { v0 += bias[col]; v1 += bias[col + 1]; }
                if (resid) {
                    float2 r = *(const float2*)(resid + (size_t)row * ldc + col);
                    v0 += r.x; v1 += r.y;
                }
                if (do_round) { v0 = tf32r(v0); v1 = tf32r(v1); }
                float2 o; o.x = v0; o.y = v1;
                *(float2*)(C + (size_t)row * ldc + col) = o;
            }
        }
    }
}

// ---------------------------------------------------------------------------
// Softmax over causal prefix L = (frame+1)*1024.  Stores tf32-rounded,
// UNNORMALIZED exp in g_S; 1/sum in g_inv (PV epilogue applies it).
// ---------------------------------------------------------------------------
__global__ void softmax_rows() {
    const int q = blockIdx.x;
    const int L = ((q >> 10) + 1) << 10;
    float* row = g_S + (size_t)q * S_TOT;
    __shared__ float red[256];
    const int tid = threadIdx.x;

    float m = -1e30f;
    for (int i = tid; i < L; i += 256) m = fmaxf(m, row[i]);
    red[tid] = m; __syncthreads();
    for (int o = 128; o > 0; o >>= 1) {
        if (tid < o) red[tid] = fmaxf(red[tid], red[tid + o]);
        __syncthreads();
    }
    m = red[0];
    __syncthreads();

    float s = 0.f;
    for (int i = tid; i < L; i += 256) {
        float e = tf32r(__expf(row[i] - m));
        row[i] = e;
        s += e;
    }
    red[tid] = s; __syncthreads();
    for (int o = 128; o > 0; o >>= 1) {
        if (tid < o) red[tid] += red[tid + o];
        __syncthreads();
    }
    if (tid == 0) g_inv[q] = 1.f / red[0];
}

// ---------------------------------------------------------------------------
// Host orchestration — kernel launches only (graph-capture safe).
// ---------------------------------------------------------------------------
extern "C" void kernel_launch(void* const* d_in, const int* in_sizes, int n_in,
                              void* d_out, int out_size) {
    (void)in_sizes; (void)n_in; (void)out_size;

    const float* in = (const float*)d_in[0];
    float* out = (float*)d_out;

    const dim3 gemm_grid(C_DIM / BN, S_TOT / BM);   // (4, 64)
    const int EW_BLOCKS = S_TOT * C_DIM / 256;      // 16384
    const int WC_BLOCKS = 27 * C_DIM * C_DIM / 256; // 27648
    const int WL_BLOCKS = C_DIM * C_DIM / 256;      // 1024
    const dim3 tb(32, 8);

    // input NCDHW [512][8192] -> channels-last g_X[8192][512]
    transpose_k<<<dim3(S_TOT / 32, C_DIM / 32), tb>>>(in, -1, nullptr, 0, C_DIM, S_TOT);

    auto resnet = [&](int base) {
        const float* n1s = (const float*)d_in[base + 0];
        const float* n1b = (const float*)d_in[base + 1];
        const float* w1  = (const float*)d_in[base + 2];
        const float* b1  = (const float*)d_in[base + 3];
        const float* n2s = (const float*)d_in[base + 4];
        const float* n2b = (const float*)d_in[base + 5];
        const float* w2  = (const float*)d_in[base + 6];
        const float* b2  = (const float*)d_in[base + 7];

        gn_stats<<<NG, 1024>>>(0);
        gn_apply<<<EW_BLOCKS, 256>>>(0, n1s, n1b, 1);
        wconv_tr<<<WC_BLOCKS, 256>>>(w1);
        mma_gemm<1><<<gemm_grid, 256>>>(1, 8, b1, -1, 2,
                                        27 * C_DIM, C_DIM, C_DIM, C_DIM, 1.f, 0);
        gn_stats<<<NG, 1024>>>(2);
        gn_apply<<<EW_BLOCKS, 256>>>(2, n2s, n2b, 1);
        wconv_tr<<<WC_BLOCKS, 256>>>(w2);
        mma_gemm<1><<<gemm_grid, 256>>>(1, 8, b2, 0, 0,
                                        27 * C_DIM, C_DIM, C_DIM, C_DIM, 1.f, 0);
    };

    // ---- resnet block 0 (inputs 1..8) ----
    resnet(1);

    // ---- causal frame attention (inputs 17..26) ----
    {
        const float* gns = (const float*)d_in[17];
        const float* gnb = (const float*)d_in[18];
        const float* wq  = (const float*)d_in[19];
        const float* bq  = (const float*)d_in[20];
        const float* wk  = (const float*)d_in[21];
        const float* bk  = (const float*)d_in[22];
        const float* wv  = (const float*)d_in[23];
        const float* bv  = (const float*)d_in[24];
        const float* wo  = (const float*)d_in[25];
        const float* bo  = (const float*)d_in[26];

        gn_stats<<<NG, 1024>>>(0);
        gn_apply<<<EW_BLOCKS, 256>>>(0, gns, gnb, 0);

        round_copy<<<WL_BLOCKS, 256>>>(wq);
        mma_gemm<0><<<gemm_grid, 256>>>(1, 9, bq, -1, 3,
                                        C_DIM, C_DIM, C_DIM, C_DIM, 1.f, 1);
        round_copy<<<WL_BLOCKS, 256>>>(wk);
        mma_gemm<0><<<gemm_grid, 256>>>(1, 9, bk, -1, 4,
                                        C_DIM, C_DIM, C_DIM, C_DIM, 1.f, 1);
        round_copy<<<WL_BLOCKS, 256>>>(wv);
        mma_gemm<0><<<gemm_grid, 256>>>(1, 9, bv, -1, 5,
                                        C_DIM, C_DIM, C_DIM, C_DIM, 1.f, 1);

        // scores: S[q,k] = scale * Q.K^T  (block-causal skip)
        const float scale = 0.044194173824159216f;  // 512^-0.5
        mma_gemm<2><<<dim3(S_TOT / BN, S_TOT / BM), 256>>>(
            3, 4, nullptr, -1, 7, C_DIM, C_DIM, C_DIM, S_TOT, scale, 0);
        softmax_rows<<<S_TOT, 256>>>();

        // Vt = V^T into g_H (tf32 values preserved)
        transpose_k<<<dim3(C_DIM / 32, S_TOT / 32), tb>>>(nullptr, 5, nullptr, 2,
                                                          S_TOT, C_DIM);
        // O = P @ V  (A = exp scores, B = Vt [c][s]); epilogue * g_inv, round
        mma_gemm<3><<<gemm_grid, 256>>>(7, 2, nullptr, -1, 6,
                                        S_TOT, S_TOT, S_TOT, C_DIM, 1.f, 1);

        round_copy<<<WL_BLOCKS, 256>>>(wo);
        mma_gemm<0><<<gemm_grid, 256>>>(6, 9, bo, 0, 0,
                                        C_DIM, C_DIM, C_DIM, C_DIM, 1.f, 0);
    }

    // ---- resnet block 1 (inputs 9..16) ----
    resnet(9);

    // channels-last g_X[8192][512] -> NCDHW out [512][8192]
    transpose_k<<<dim3(C_DIM / 32, S_TOT / 32), tb>>>(nullptr, 0, out, -1, S_TOT, C_DIM);
}